// round 12
// baseline (speedup 1.0000x reference)
#include <cuda_runtime.h>

// IF spiking neuron forward:
//   mem0 = dtmem * thresh
//   for t: mem += x_t; spike = (mem >= thresh) ? thresh : 0; mem -= spike
//
// FINAL (R5 structure — best measured bench 123.97us; whole R4-R10 family is
// pinned at the sm_103a LTS throughput cap, ~6.65 TB/s over the ~780MB
// algorithmic traffic floor):
//  - one thread per (batch, feature-vec4) site; T loop fully in registers
//  - grid.x = B (fast launch dim): the 8 blocks sharing a feature chunk's
//    thresh/dtmem launch adjacently -> param reads L2-served
//  - 4 x-loads front-batched (MLP=6 with params); stores interleaved with
//    the per-step compute (benched marginally better than write-bursting)
//  - default cache policy (.cs hints measured ~6% BW penalty in R2-R4)
//  - 32-bit indexing: all element offsets < 2^31 for this shape

#define T_STEPS 4

__global__ __launch_bounds__(256, 7) void if_fwd_kernel(
    const float4* __restrict__ x,      // [T, B, feat_v]
    const float4* __restrict__ thresh, // [feat_v]
    const float4* __restrict__ dtmem,  // [feat_v]
    float4* __restrict__ out,          // [T, B, feat_v]
    int feat_v,                        // 1024*3072/4
    int n_per_t_v)                     // B*feat_v (t-stride in vec4)
{
    int f = blockIdx.y * blockDim.x + threadIdx.x;
    if (f >= feat_v) return;

    int b = blockIdx.x;
    int base = b * feat_v + f;         // max ~6.3M, fits int

    // Front-batch the 4 independent time-step loads + params.
    float4 xv0 = __ldg(&x[base]);
    float4 xv1 = __ldg(&x[base + n_per_t_v]);
    float4 xv2 = __ldg(&x[base + 2 * n_per_t_v]);
    float4 xv3 = __ldg(&x[base + 3 * n_per_t_v]);

    float4 th = __ldg(&thresh[f]);
    float4 dm = __ldg(&dtmem[f]);

    float4 mem;
    mem.x = dm.x * th.x;
    mem.y = dm.y * th.y;
    mem.z = dm.z * th.z;
    mem.w = dm.w * th.w;

    float4 sp;

#define STEP(xv, tidx)                                                      \
    mem.x += xv.x; sp.x = (mem.x >= th.x) ? th.x : 0.0f; mem.x -= sp.x;     \
    mem.y += xv.y; sp.y = (mem.y >= th.y) ? th.y : 0.0f; mem.y -= sp.y;     \
    mem.z += xv.z; sp.z = (mem.z >= th.z) ? th.z : 0.0f; mem.z -= sp.z;     \
    mem.w += xv.w; sp.w = (mem.w >= th.w) ? th.w : 0.0f; mem.w -= sp.w;     \
    out[base + (tidx) * n_per_t_v] = sp;

    STEP(xv0, 0)
    STEP(xv1, 1)
    STEP(xv2, 2)
    STEP(xv3, 3)
#undef STEP
}

extern "C" void kernel_launch(void* const* d_in, const int* in_sizes, int n_in,
                              void* d_out, int out_size) {
    const float* x      = (const float*)d_in[0];
    const float* thresh = (const float*)d_in[1];
    const float* dtmem  = (const float*)d_in[2];
    float* out          = (float*)d_out;

    int total  = in_sizes[0];           // T*B*1024*3072
    int feat_n = in_sizes[1];           // 1024*3072
    int B      = total / (T_STEPS * feat_n);

    int feat_v    = feat_n / 4;
    int n_per_t_v = B * feat_v;

    int threads = 256;
    dim3 grid(B, (feat_v + threads - 1) / threads);

    if_fwd_kernel<<<grid, threads>>>(
        (const float4*)x, (const float4*)thresh, (const float4*)dtmem,
        (float4*)out, feat_v, n_per_t_v);
}

// round 13
// speedup vs baseline: 1.0005x; 1.0005x over previous
#include <cuda_runtime.h>

// IF spiking neuron forward:
//   mem0 = dtmem * thresh
//   for t: mem += x_t; spike = (mem >= thresh) ? thresh : 0; mem -= spike
//
// CONVERGED FINAL. The R4-R12 sweep (occ 53-84%, MLP 4-8, block 256/512,
// store scheduling, cache hints, addressing width) holds bench at 124-125us
// and DRAM BW at 6.6-6.7 TB/s over ~780MB — the algorithmic traffic floor
// (x read once, out written once, params L2-served) at the HBM mixed
// read/write efficiency ceiling (~83% of pin rate). Structure:
//  - one thread per (batch, feature-vec4) site; T loop fully in registers
//  - grid.x = B (fast launch dim): the 8 blocks sharing a feature chunk's
//    thresh/dtmem launch adjacently -> param reads L2-served
//  - 4 x-loads front-batched (MLP=6 with params); stores interleaved
//  - default cache policy (.cs hints cost ~2% BW, measured R2-R5)
//  - 32-bit indexing (all vec4 offsets < 2^31 for this shape)

#define T_STEPS 4

__global__ __launch_bounds__(256, 7) void if_fwd_kernel(
    const float4* __restrict__ x,      // [T, B, feat_v]
    const float4* __restrict__ thresh, // [feat_v]
    const float4* __restrict__ dtmem,  // [feat_v]
    float4* __restrict__ out,          // [T, B, feat_v]
    int feat_v,                        // 1024*3072/4
    int n_per_t_v)                     // B*feat_v (t-stride in vec4)
{
    int f = blockIdx.y * blockDim.x + threadIdx.x;
    if (f >= feat_v) return;

    int b = blockIdx.x;
    int base = b * feat_v + f;

    // Front-batch the 4 independent time-step loads + params.
    float4 xv0 = __ldg(&x[base]);
    float4 xv1 = __ldg(&x[base + n_per_t_v]);
    float4 xv2 = __ldg(&x[base + 2 * n_per_t_v]);
    float4 xv3 = __ldg(&x[base + 3 * n_per_t_v]);

    float4 th = __ldg(&thresh[f]);
    float4 dm = __ldg(&dtmem[f]);

    float4 mem;
    mem.x = dm.x * th.x;
    mem.y = dm.y * th.y;
    mem.z = dm.z * th.z;
    mem.w = dm.w * th.w;

    float4 sp;

#define STEP(xv, tidx)                                                      \
    mem.x += xv.x; sp.x = (mem.x >= th.x) ? th.x : 0.0f; mem.x -= sp.x;     \
    mem.y += xv.y; sp.y = (mem.y >= th.y) ? th.y : 0.0f; mem.y -= sp.y;     \
    mem.z += xv.z; sp.z = (mem.z >= th.z) ? th.z : 0.0f; mem.z -= sp.z;     \
    mem.w += xv.w; sp.w = (mem.w >= th.w) ? th.w : 0.0f; mem.w -= sp.w;     \
    out[base + (tidx) * n_per_t_v] = sp;

    STEP(xv0, 0)
    STEP(xv1, 1)
    STEP(xv2, 2)
    STEP(xv3, 3)
#undef STEP
}

extern "C" void kernel_launch(void* const* d_in, const int* in_sizes, int n_in,
                              void* d_out, int out_size) {
    const float* x      = (const float*)d_in[0];
    const float* thresh = (const float*)d_in[1];
    const float* dtmem  = (const float*)d_in[2];
    float* out          = (float*)d_out;

    int total  = in_sizes[0];           // T*B*1024*3072
    int feat_n = in_sizes[1];           // 1024*3072
    int B      = total / (T_STEPS * feat_n);

    int feat_v    = feat_n / 4;
    int n_per_t_v = B * feat_v;

    int threads = 256;
    dim3 grid(B, (feat_v + threads - 1) / threads);

    if_fwd_kernel<<<grid, threads>>>(
        (const float4*)x, (const float4*)thresh, (const float4*)dtmem,
        (float4*)out, feat_v, n_per_t_v);
}